// round 5
// baseline (speedup 1.0000x reference)
#include <cuda_runtime.h>
#include <cstdint>

#define NB    2
#define DIM   256
#define RES   256
#define FWS   8
#define HEADS 8
#define HD    32
#define NPX   64        // FWS*FWS
#define NWIN  512       // NB * 16 * 16
#define SCALE 0.17677669529663687f

// ---- scratch (device globals; no allocation) ----
__device__ float g_ll   [NWIN * DIM * NPX];
__device__ float g_lh   [NWIN * DIM * NPX];
__device__ float g_hl   [NWIN * DIM * NPX];
__device__ float g_hh   [NWIN * DIM * NPX];
__device__ float g_llout[NWIN * DIM * NPX];
__device__ float g_attn [NWIN * HEADS * NPX * NPX];          // [win][head][n][m]
__device__ float g_pout [DIM * NWIN * NPX];                  // [c][win*64+px], relu'd

__device__ __forceinline__ void ffma2(uint64_t& acc, uint64_t a, uint64_t b) {
    asm("fma.rn.f32x2 %0, %1, %2, %0;" : "+l"(acc) : "l"(a), "l"(b));
}
__device__ __forceinline__ float hsum2(uint64_t v) {
    float lo, hi;
    asm("mov.b64 {%0,%1}, %2;" : "=f"(lo), "=f"(hi) : "l"(v));
    return lo + hi;
}
__device__ __forceinline__ uint64_t dup2(float w) {
    uint64_t r;
    asm("mov.b64 %0, {%1,%1};" : "=l"(r) : "f"(w));
    return r;
}
__device__ __forceinline__ float2 unp2(uint64_t v) {
    float lo, hi;
    asm("mov.b64 {%0,%1}, %2;" : "=f"(lo), "=f"(hi) : "l"(v));
    return make_float2(lo, hi);
}

// ============================================================
// K1: forward wavelet -> windowed layout. 2 horizontal px per thread (float4 loads)
// ============================================================
__global__ void k_fwt(const float* __restrict__ x, const float* __restrict__ wt) {
    int tid = blockIdx.x * blockDim.x + threadIdx.x;   // over NWIN*DIM*32
    int p   = tid & 31;            // r*4 + c2
    int ch  = (tid >> 5) & 255;
    int win = tid >> 13;
    int b   = win >> 8;
    int wy  = (win >> 4) & 15;
    int wx  = win & 15;
    int r = p >> 2, c2 = p & 3;
    int Y = (wy * 8 + r) * 2;
    int X = (wx * 8 + c2 * 2) * 2;
    const float* xb = x + (((size_t)(b * DIM + ch) * RES + Y) * RES + X);
    float4 a0 = *(const float4*)xb;
    float4 a1 = *(const float4*)(xb + RES);
    const float* w = wt + ch * 16;   // [s][dy][dx]
    int obase = (win * DIM + ch) * NPX + r * 8 + c2 * 2;
    #pragma unroll
    for (int s = 0; s < 4; s++) {
        float w0 = w[4*s], w1 = w[4*s+1], w2 = w[4*s+2], w3 = w[4*s+3];
        float v0 = a0.x*w0 + a0.y*w1 + a1.x*w2 + a1.y*w3;
        float v1 = a0.z*w0 + a0.w*w1 + a1.z*w2 + a1.w*w3;
        float2 vv = make_float2(v0, v1);
        float* dst = (s == 0) ? g_ll : (s == 1) ? g_lh : (s == 2) ? g_hl : g_hh;
        *(float2*)(dst + obase) = vv;
    }
}

// ============================================================
// K2a: attention matrices, one block per (window, head)
// ============================================================
__global__ void __launch_bounds__(256) k_attnmat(
    const float* __restrict__ dww, const float* __restrict__ dwb,
    const float* __restrict__ ab,  const int* __restrict__ bidx)
{
    __shared__ float s_lh[HD * 66];
    __shared__ float s_k [NPX * 34];
    __shared__ float s_q [NPX * 34];

    const int t = threadIdx.x;
    const int bw = blockIdx.x;
    const int win = bw >> 3, h = bw & 7;
    const size_t base = (size_t)win * DIM * NPX + h * HD * NPX;
    const float* lsrc = g_lh + base;
    const float* ksrc = g_hl + base;
    #pragma unroll
    for (int i = 0; i < 8; i++) {
        int idx = t + 256 * i;
        int d = idx >> 6, m = idx & 63;
        s_lh[d * 66 + m] = lsrc[idx];
        s_k [m * 34 + d] = ksrc[idx];
    }
    __syncthreads();

    // q = depthwise 5x5 conv (zero pad outside window) + bias
    {
        int d = t >> 3, r = t & 7;
        const float* wq = dww + (h * HD + d) * 25;
        float wreg[25];
        #pragma unroll
        for (int i = 0; i < 25; i++) wreg[i] = wq[i];
        float bq = dwb[h * HD + d];
        const float* lr = s_lh + d * 66;
        #pragma unroll
        for (int c = 0; c < 8; c++) {
            float acc = bq;
            #pragma unroll
            for (int u = 0; u < 5; u++) {
                int rr = r + u - 2;
                if (rr < 0 || rr > 7) continue;
                #pragma unroll
                for (int v = 0; v < 5; v++) {
                    int cc = c + v - 2;
                    if (cc < 0 || cc > 7) continue;
                    acc += lr[rr * 8 + cc] * wreg[u * 5 + v];
                }
            }
            s_q[(r * 8 + c) * 34 + d] = acc;
        }
    }
    __syncthreads();

    // logits + softmax: thread (n = t>>2, q = t&3), m = q + 4*mm (bank-conflict-free)
    {
        int n = t >> 2, q = t & 3;
        uint64_t q2[16];
        const float* qrow = s_q + n * 34;
        #pragma unroll
        for (int i = 0; i < 16; i++) q2[i] = *(const uint64_t*)(qrow + 2 * i);
        const int* brow = bidx + n * 64;
        const float* abh = ab + h * 64;
        float logits[16];
        #pragma unroll
        for (int mm = 0; mm < 16; mm++) {
            int m = q + 4 * mm;
            const float* krow = s_k + m * 34;
            uint64_t acc = 0ull;
            #pragma unroll
            for (int i = 0; i < 16; i++) {
                uint64_t k2 = *(const uint64_t*)(krow + 2 * i);
                ffma2(acc, q2[i], k2);
            }
            logits[mm] = hsum2(acc) * SCALE + abh[brow[m]];
        }
        float mx = logits[0];
        #pragma unroll
        for (int i = 1; i < 16; i++) mx = fmaxf(mx, logits[i]);
        mx = fmaxf(mx, __shfl_xor_sync(0xffffffffu, mx, 1));
        mx = fmaxf(mx, __shfl_xor_sync(0xffffffffu, mx, 2));
        float sum = 0.f;
        #pragma unroll
        for (int i = 0; i < 16; i++) { logits[i] = __expf(logits[i] - mx); sum += logits[i]; }
        sum += __shfl_xor_sync(0xffffffffu, sum, 1);
        sum += __shfl_xor_sync(0xffffffffu, sum, 2);
        float inv = 1.0f / sum;
        float* arow = g_attn + ((size_t)bw * 64 + n) * 64;
        #pragma unroll
        for (int mm = 0; mm < 16; mm++) arow[q + 4 * mm] = logits[mm] * inv;
    }
}

// ============================================================
// K2b: sequential head recurrence (V path), one block per window
// ============================================================
__global__ void __launch_bounds__(256) k_vrec() {
    __shared__ float s_v[HD * 66];
    __shared__ float s_a[NPX * 66];

    const int t = threadIdx.x;
    const int win = blockIdx.x;
    const size_t wbase = (size_t)win * DIM * NPX;
    const int d = t >> 3, j = t & 7;

    for (int h = 0; h < HEADS; h++) {
        __syncthreads();
        // stage attn tile for this head
        const float* asrc = g_attn + ((size_t)(win * 8 + h)) * 4096;
        #pragma unroll
        for (int i = 0; i < 16; i++) {
            int idx = t + 256 * i;
            int n = idx >> 6, m = idx & 63;
            s_a[n * 66 + m] = asrc[idx];
        }
        // v update
        const float* vsrc = g_ll + wbase + h * HD * NPX;
        #pragma unroll
        for (int i = 0; i < 8; i++) {
            int idx = t + 256 * i;
            int dd = idx >> 6, m = idx & 63;
            if (h == 0) s_v[dd * 66 + m]  = vsrc[idx];
            else        s_v[dd * 66 + m] += vsrc[idx];
        }
        __syncthreads();

        uint64_t acc2[8];
        #pragma unroll
        for (int i = 0; i < 8; i++) acc2[i] = 0ull;
        const float* vrow = s_v + d * 66;
        const float* ajb  = s_a + j * 66;
        #pragma unroll 8
        for (int mp = 0; mp < 32; mp++) {
            uint64_t v2 = *(const uint64_t*)(vrow + 2 * mp);
            #pragma unroll
            for (int i = 0; i < 8; i++) {
                uint64_t a2 = *(const uint64_t*)(ajb + (8 * i) * 66 + 2 * mp);
                ffma2(acc2[i], v2, a2);
            }
        }
        __syncthreads();   // all reads of s_v done before overwrite

        float* prow = g_pout + (size_t)(h * HD + d) * (NWIN * NPX) + win * NPX;
        #pragma unroll
        for (int i = 0; i < 8; i++) {
            float o = hsum2(acc2[i]);
            int nn = 8 * i + j;
            s_v[d * 66 + nn] = o;          // recurrence uses pre-relu
            prow[nn] = fmaxf(o, 0.f);      // projection input is relu'd
        }
    }
}

// ============================================================
// K2c: 256x256 projection. One block per window; thread = 8 oc x 8 px.
// Weights staged via smem in 32-k chunks, layout s_w[o][36] (conflict-free).
// ============================================================
#define SIN_STRIDE 68
#define SW_STRIDE  36
#define SIN_FLOATS (DIM * SIN_STRIDE)        // 17408
#define SW_FLOATS  (DIM * SW_STRIDE)         // 9216
#define PROJ_SMEM  ((SIN_FLOATS + SW_FLOATS) * 4)   // 106,496 B

__global__ void __launch_bounds__(256, 2) k_proj(
    const float* __restrict__ pw, const float* __restrict__ pb)
{
    extern __shared__ float sm[];
    float* s_in = sm;                 // [256 k][68]
    float* s_w  = sm + SIN_FLOATS;    // [256 o][36] (32 k per chunk + pad)

    const int t = threadIdx.x;
    const int win = blockIdx.x;

    // stage relu'd attention output [256 ch][64 px] for this window (float4)
    {
        const float* src = g_pout + win * NPX;
        #pragma unroll
        for (int i = 0; i < 16; i++) {
            int flat = t + 256 * i;           // over 4096 float4
            int c = flat >> 4, p4 = flat & 15;
            float4 v = *(const float4*)(src + (size_t)c * (NWIN * NPX) + p4 * 4);
            *(float4*)(s_in + c * SIN_STRIDE + p4 * 4) = v;
        }
    }

    const int ocg = t >> 3;           // 0..31 -> 8 output channels each
    const int pxg = t & 7;            // 0..7  -> 8 px each
    const float* sbase = s_in + pxg * 8;

    uint64_t acc[8][4];
    #pragma unroll
    for (int j = 0; j < 8; j++)
        #pragma unroll
        for (int i = 0; i < 4; i++) acc[j][i] = 0ull;

    for (int kc = 0; kc < 8; kc++) {
        __syncthreads();
        // stage weight chunk: w[o][kc*32 .. +32] -> s_w[o][0..32]
        #pragma unroll
        for (int i = 0; i < 8; i++) {
            int flat = t + 256 * i;           // over 2048 float4
            int o = flat >> 3, c4 = flat & 7;
            float4 wv = *(const float4*)(pw + o * 256 + kc * 32 + c4 * 4);
            *(float4*)(s_w + o * SW_STRIDE + c4 * 4) = wv;
        }
        __syncthreads();

        #pragma unroll 2
        for (int k4 = 0; k4 < 8; k4++) {
            float4 w4[8];
            #pragma unroll
            for (int j = 0; j < 8; j++)
                w4[j] = *(const float4*)(s_w + (ocg * 8 + j) * SW_STRIDE + k4 * 4);
            #pragma unroll
            for (int kk = 0; kk < 4; kk++) {
                const float* srow = sbase + (kc * 32 + k4 * 4 + kk) * SIN_STRIDE;
                ulonglong2 v0 = *(const ulonglong2*)(srow);
                ulonglong2 v1 = *(const ulonglong2*)(srow + 4);
                #pragma unroll
                for (int j = 0; j < 8; j++) {
                    float wj = ((const float*)&w4[j])[kk];
                    uint64_t wd = dup2(wj);
                    ffma2(acc[j][0], v0.x, wd);
                    ffma2(acc[j][1], v0.y, wd);
                    ffma2(acc[j][2], v1.x, wd);
                    ffma2(acc[j][3], v1.y, wd);
                }
            }
        }
    }

    // bias + store directly to g_llout
    float* wdst = g_llout + (size_t)win * DIM * NPX;
    #pragma unroll
    for (int j = 0; j < 8; j++) {
        int oc = ocg * 8 + j;
        float bias = pb[oc];
        float* dst = wdst + oc * NPX + pxg * 8;
        float2 a = unp2(acc[j][0]);
        float2 b = unp2(acc[j][1]);
        float2 c = unp2(acc[j][2]);
        float2 d = unp2(acc[j][3]);
        float4 lo4 = make_float4(a.x + bias, a.y + bias, b.x + bias, b.y + bias);
        float4 hi4 = make_float4(c.x + bias, c.y + bias, d.x + bias, d.y + bias);
        *(float4*)(dst)     = lo4;
        *(float4*)(dst + 4) = hi4;
    }
}

// ============================================================
// K3: inverse wavelet (lhs_dilation conv collapses to parity-indexed taps)
// ============================================================
__global__ void k_iwt(const float* __restrict__ iwt, float* __restrict__ out) {
    int tid = blockIdx.x * blockDim.x + threadIdx.x;   // over NB*DIM*RES*RES
    int X  = tid & 255;
    int Y  = (tid >> 8) & 255;
    int ch = (tid >> 16) & 255;
    int b  = tid >> 24;
    int y = Y >> 1, x = X >> 1;
    int win = (b * 16 + (y >> 3)) * 16 + (x >> 3);
    int px  = (y & 7) * 8 + (x & 7);
    int base = (win * DIM + ch) * NPX + px;
    const float* w = iwt + ch * 16 + (Y & 1) * 2 + (X & 1);
    float v = g_llout[base] * w[0] + g_lh[base] * w[4]
            + g_hl[base]   * w[8] + g_hh[base] * w[12];
    out[tid] = v;
}

// ============================================================
extern "C" void kernel_launch(void* const* d_in, const int* in_sizes, int n_in,
                              void* d_out, int out_size) {
    const float* x   = (const float*)d_in[0];
    const float* wt  = (const float*)d_in[1];
    const float* iwt = (const float*)d_in[2];
    const float* dww = (const float*)d_in[3];
    const float* dwb = (const float*)d_in[4];
    const float* pw  = (const float*)d_in[5];
    const float* pb  = (const float*)d_in[6];
    const float* ab  = (const float*)d_in[7];
    const int*   bidx= (const int*)d_in[8];
    float* out = (float*)d_out;

    (void)in_sizes; (void)n_in; (void)out_size;

    cudaFuncSetAttribute(k_proj, cudaFuncAttributeMaxDynamicSharedMemorySize, PROJ_SMEM);

    k_fwt    <<<(NWIN * DIM * 32) / 256, 256>>>(x, wt);
    k_attnmat<<<NWIN * HEADS, 256>>>(dww, dwb, ab, bidx);
    k_vrec   <<<NWIN, 256>>>();
    k_proj   <<<NWIN, 256, PROJ_SMEM>>>(pw, pb);
    k_iwt    <<<(NB * DIM * RES * RES) / 256, 256>>>(iwt, out);
}

// round 6
// speedup vs baseline: 1.6404x; 1.6404x over previous
#include <cuda_runtime.h>
#include <cuda_bf16.h>
#include <mma.h>
#include <cstdint>

using namespace nvcuda;

#define NB    2
#define DIM   256
#define RES   256
#define FWS   8
#define HEADS 8
#define HD    32
#define NPX   64        // FWS*FWS
#define NWIN  512       // NB * 16 * 16
#define SCALE 0.17677669529663687f

// ---- scratch (device globals; no allocation) ----
__device__ float g_ll   [NWIN * DIM * NPX];
__device__ float g_lh   [NWIN * DIM * NPX];
__device__ float g_hl   [NWIN * DIM * NPX];
__device__ float g_hh   [NWIN * DIM * NPX];
__device__ float g_llout[NWIN * DIM * NPX];            // proj WITHOUT bias (bias folded into k_iwt)
__device__ float g_attn [NWIN * HEADS * NPX * NPX];    // [win][head][n][m]
__device__ __nv_bfloat16 g_xhi[NWIN * DIM * NPX];      // [win][c][px] relu'd, hi part
__device__ __nv_bfloat16 g_xlo[NWIN * DIM * NPX];      // lo part
__device__ __nv_bfloat16 g_whi[DIM * DIM];             // [oc][k]
__device__ __nv_bfloat16 g_wlo[DIM * DIM];

__device__ __forceinline__ void ffma2(uint64_t& acc, uint64_t a, uint64_t b) {
    asm("fma.rn.f32x2 %0, %1, %2, %0;" : "+l"(acc) : "l"(a), "l"(b));
}
__device__ __forceinline__ float hsum2(uint64_t v) {
    float lo, hi;
    asm("mov.b64 {%0,%1}, %2;" : "=f"(lo), "=f"(hi) : "l"(v));
    return lo + hi;
}

// ============================================================
// K0: split projection weights into bf16 hi/lo
// ============================================================
__global__ void k_wsplit(const float* __restrict__ pw) {
    int tid = blockIdx.x * blockDim.x + threadIdx.x;   // over 65536
    float w = pw[tid];
    __nv_bfloat16 hi = __float2bfloat16(w);
    float lo = w - __bfloat162float(hi);
    g_whi[tid] = hi;
    g_wlo[tid] = __float2bfloat16(lo);
}

// ============================================================
// K1: forward wavelet -> windowed layout. 2 horizontal px per thread (float4 loads)
// ============================================================
__global__ void k_fwt(const float* __restrict__ x, const float* __restrict__ wt) {
    int tid = blockIdx.x * blockDim.x + threadIdx.x;   // over NWIN*DIM*32
    int p   = tid & 31;            // r*4 + c2
    int ch  = (tid >> 5) & 255;
    int win = tid >> 13;
    int b   = win >> 8;
    int wy  = (win >> 4) & 15;
    int wx  = win & 15;
    int r = p >> 2, c2 = p & 3;
    int Y = (wy * 8 + r) * 2;
    int X = (wx * 8 + c2 * 2) * 2;
    const float* xb = x + (((size_t)(b * DIM + ch) * RES + Y) * RES + X);
    float4 a0 = *(const float4*)xb;
    float4 a1 = *(const float4*)(xb + RES);
    const float* w = wt + ch * 16;   // [s][dy][dx]
    int obase = (win * DIM + ch) * NPX + r * 8 + c2 * 2;
    #pragma unroll
    for (int s = 0; s < 4; s++) {
        float w0 = w[4*s], w1 = w[4*s+1], w2 = w[4*s+2], w3 = w[4*s+3];
        float v0 = a0.x*w0 + a0.y*w1 + a1.x*w2 + a1.y*w3;
        float v1 = a0.z*w0 + a0.w*w1 + a1.z*w2 + a1.w*w3;
        float2 vv = make_float2(v0, v1);
        float* dst = (s == 0) ? g_ll : (s == 1) ? g_lh : (s == 2) ? g_hl : g_hh;
        *(float2*)(dst + obase) = vv;
    }
}

// ============================================================
// K2a: attention matrices, one block per (window, head)
// ============================================================
__global__ void __launch_bounds__(256) k_attnmat(
    const float* __restrict__ dww, const float* __restrict__ dwb,
    const float* __restrict__ ab,  const int* __restrict__ bidx)
{
    __shared__ float s_lh[HD * 66];
    __shared__ float s_k [NPX * 34];
    __shared__ float s_q [NPX * 34];

    const int t = threadIdx.x;
    const int bw = blockIdx.x;
    const int win = bw >> 3, h = bw & 7;
    const size_t base = (size_t)win * DIM * NPX + h * HD * NPX;
    const float* lsrc = g_lh + base;
    const float* ksrc = g_hl + base;
    #pragma unroll
    for (int i = 0; i < 8; i++) {
        int idx = t + 256 * i;
        int d = idx >> 6, m = idx & 63;
        s_lh[d * 66 + m] = lsrc[idx];
        s_k [m * 34 + d] = ksrc[idx];
    }
    __syncthreads();

    // q = depthwise 5x5 conv (zero pad outside window) + bias
    {
        int d = t >> 3, r = t & 7;
        const float* wq = dww + (h * HD + d) * 25;
        float wreg[25];
        #pragma unroll
        for (int i = 0; i < 25; i++) wreg[i] = wq[i];
        float bq = dwb[h * HD + d];
        const float* lr = s_lh + d * 66;
        #pragma unroll
        for (int c = 0; c < 8; c++) {
            float acc = bq;
            #pragma unroll
            for (int u = 0; u < 5; u++) {
                int rr = r + u - 2;
                if (rr < 0 || rr > 7) continue;
                #pragma unroll
                for (int v = 0; v < 5; v++) {
                    int cc = c + v - 2;
                    if (cc < 0 || cc > 7) continue;
                    acc += lr[rr * 8 + cc] * wreg[u * 5 + v];
                }
            }
            s_q[(r * 8 + c) * 34 + d] = acc;
        }
    }
    __syncthreads();

    // logits + softmax: thread (n = t>>2, q = t&3), m = q + 4*mm (bank-conflict-free)
    {
        int n = t >> 2, q = t & 3;
        uint64_t q2[16];
        const float* qrow = s_q + n * 34;
        #pragma unroll
        for (int i = 0; i < 16; i++) q2[i] = *(const uint64_t*)(qrow + 2 * i);
        const int* brow = bidx + n * 64;
        const float* abh = ab + h * 64;
        float logits[16];
        #pragma unroll
        for (int mm = 0; mm < 16; mm++) {
            int m = q + 4 * mm;
            const float* krow = s_k + m * 34;
            uint64_t acc = 0ull;
            #pragma unroll
            for (int i = 0; i < 16; i++) {
                uint64_t k2 = *(const uint64_t*)(krow + 2 * i);
                ffma2(acc, q2[i], k2);
            }
            logits[mm] = hsum2(acc) * SCALE + abh[brow[m]];
        }
        float mx = logits[0];
        #pragma unroll
        for (int i = 1; i < 16; i++) mx = fmaxf(mx, logits[i]);
        mx = fmaxf(mx, __shfl_xor_sync(0xffffffffu, mx, 1));
        mx = fmaxf(mx, __shfl_xor_sync(0xffffffffu, mx, 2));
        float sum = 0.f;
        #pragma unroll
        for (int i = 0; i < 16; i++) { logits[i] = __expf(logits[i] - mx); sum += logits[i]; }
        sum += __shfl_xor_sync(0xffffffffu, sum, 1);
        sum += __shfl_xor_sync(0xffffffffu, sum, 2);
        float inv = 1.0f / sum;
        float* arow = g_attn + ((size_t)bw * 64 + n) * 64;
        #pragma unroll
        for (int mm = 0; mm < 16; mm++) arow[q + 4 * mm] = logits[mm] * inv;
    }
}

// ============================================================
// K2b: sequential head recurrence (V path), one block per window.
// Epilogue emits relu'd output as bf16 hi/lo splits for the tensor-core proj.
// ============================================================
__global__ void __launch_bounds__(256) k_vrec() {
    __shared__ float s_v[HD * 66];
    __shared__ float s_a[NPX * 66];

    const int t = threadIdx.x;
    const int win = blockIdx.x;
    const size_t wbase = (size_t)win * DIM * NPX;
    const int d = t >> 3, j = t & 7;

    for (int h = 0; h < HEADS; h++) {
        __syncthreads();
        // stage attn tile for this head
        const float* asrc = g_attn + ((size_t)(win * 8 + h)) * 4096;
        #pragma unroll
        for (int i = 0; i < 16; i++) {
            int idx = t + 256 * i;
            int n = idx >> 6, m = idx & 63;
            s_a[n * 66 + m] = asrc[idx];
        }
        // v update
        const float* vsrc = g_ll + wbase + h * HD * NPX;
        #pragma unroll
        for (int i = 0; i < 8; i++) {
            int idx = t + 256 * i;
            int dd = idx >> 6, m = idx & 63;
            if (h == 0) s_v[dd * 66 + m]  = vsrc[idx];
            else        s_v[dd * 66 + m] += vsrc[idx];
        }
        __syncthreads();

        uint64_t acc2[8];
        #pragma unroll
        for (int i = 0; i < 8; i++) acc2[i] = 0ull;
        const float* vrow = s_v + d * 66;
        const float* ajb  = s_a + j * 66;
        #pragma unroll 8
        for (int mp = 0; mp < 32; mp++) {
            uint64_t v2 = *(const uint64_t*)(vrow + 2 * mp);
            #pragma unroll
            for (int i = 0; i < 8; i++) {
                uint64_t a2 = *(const uint64_t*)(ajb + (8 * i) * 66 + 2 * mp);
                ffma2(acc2[i], v2, a2);
            }
        }
        __syncthreads();   // all reads of s_v done before overwrite

        __nv_bfloat16* xh = g_xhi + wbase + (h * HD + d) * NPX;
        __nv_bfloat16* xl = g_xlo + wbase + (h * HD + d) * NPX;
        #pragma unroll
        for (int i = 0; i < 8; i++) {
            float o = hsum2(acc2[i]);
            int nn = 8 * i + j;
            s_v[d * 66 + nn] = o;               // recurrence uses pre-relu
            float ro = fmaxf(o, 0.f);           // projection input is relu'd
            __nv_bfloat16 hb = __float2bfloat16(ro);
            float lof = ro - __bfloat162float(hb);
            xh[nn] = hb;
            xl[nn] = __float2bfloat16(lof);
        }
    }
}

// ============================================================
// K2c: 256x256 projection on tensor cores (bf16 WMMA, 3-term hi/lo split).
// Block = window (8 warps); warp = 32 oc x 64 px. W tiles read from L2,
// X staged in smem [256][72] bf16 (conflict-free LDSM).
// ============================================================
#define XLD 72
#define PROJ_SMEM (2 * DIM * XLD * 2)   // hi+lo, bf16 -> 73,728 B

__global__ void __launch_bounds__(256, 2) k_proj() {
    extern __shared__ __nv_bfloat16 sx[];
    __nv_bfloat16* s_hi = sx;              // [256][72]
    __nv_bfloat16* s_lo = sx + DIM * XLD;  // [256][72]

    const int t = threadIdx.x;
    const int win = blockIdx.x;
    const size_t xbase = (size_t)win * DIM * NPX;

    // stage X hi/lo (each 16384 bf16 = 2048 uint4)
    {
        const uint4* shi = (const uint4*)(g_xhi + xbase);
        const uint4* slo = (const uint4*)(g_xlo + xbase);
        #pragma unroll
        for (int i = 0; i < 8; i++) {
            int flat = t + 256 * i;
            int row = flat >> 3, col = (flat & 7) * 8;
            *(uint4*)(s_hi + row * XLD + col) = shi[flat];
            *(uint4*)(s_lo + row * XLD + col) = slo[flat];
        }
    }
    __syncthreads();

    const int wid = t >> 5;
    const int ocb = wid * 32;

    wmma::fragment<wmma::accumulator, 16, 16, 16, float> c[2][4];
    #pragma unroll
    for (int mi = 0; mi < 2; mi++)
        #pragma unroll
        for (int ni = 0; ni < 4; ni++)
            wmma::fill_fragment(c[mi][ni], 0.0f);

    for (int kt = 0; kt < 16; kt++) {
        wmma::fragment<wmma::matrix_a, 16, 16, 16, __nv_bfloat16, wmma::row_major> ahi[2], alo[2];
        #pragma unroll
        for (int mi = 0; mi < 2; mi++) {
            wmma::load_matrix_sync(ahi[mi], g_whi + (ocb + mi * 16) * 256 + kt * 16, 256);
            wmma::load_matrix_sync(alo[mi], g_wlo + (ocb + mi * 16) * 256 + kt * 16, 256);
        }
        #pragma unroll
        for (int ni = 0; ni < 4; ni++) {
            wmma::fragment<wmma::matrix_b, 16, 16, 16, __nv_bfloat16, wmma::row_major> bhi, blo;
            wmma::load_matrix_sync(bhi, s_hi + (kt * 16) * XLD + ni * 16, XLD);
            wmma::load_matrix_sync(blo, s_lo + (kt * 16) * XLD + ni * 16, XLD);
            #pragma unroll
            for (int mi = 0; mi < 2; mi++) {
                wmma::mma_sync(c[mi][ni], ahi[mi], bhi, c[mi][ni]);
                wmma::mma_sync(c[mi][ni], ahi[mi], blo, c[mi][ni]);
                wmma::mma_sync(c[mi][ni], alo[mi], bhi, c[mi][ni]);
            }
        }
    }

    float* dst = g_llout + xbase;
    #pragma unroll
    for (int mi = 0; mi < 2; mi++)
        #pragma unroll
        for (int ni = 0; ni < 4; ni++)
            wmma::store_matrix_sync(dst + (ocb + mi * 16) * NPX + ni * 16,
                                    c[mi][ni], NPX, wmma::mem_row_major);
}

// ============================================================
// K3: inverse wavelet; projection bias pb[ch] folded in here
// ============================================================
__global__ void k_iwt(const float* __restrict__ iwt, const float* __restrict__ pb,
                      float* __restrict__ out) {
    int tid = blockIdx.x * blockDim.x + threadIdx.x;   // over NB*DIM*RES*RES
    int X  = tid & 255;
    int Y  = (tid >> 8) & 255;
    int ch = (tid >> 16) & 255;
    int b  = tid >> 24;
    int y = Y >> 1, x = X >> 1;
    int win = (b * 16 + (y >> 3)) * 16 + (x >> 3);
    int px  = (y & 7) * 8 + (x & 7);
    int base = (win * DIM + ch) * NPX + px;
    const float* w = iwt + ch * 16 + (Y & 1) * 2 + (X & 1);
    float ll = g_llout[base] + pb[ch];
    float v = ll * w[0] + g_lh[base] * w[4]
            + g_hl[base] * w[8] + g_hh[base] * w[12];
    out[tid] = v;
}

// ============================================================
extern "C" void kernel_launch(void* const* d_in, const int* in_sizes, int n_in,
                              void* d_out, int out_size) {
    const float* x   = (const float*)d_in[0];
    const float* wt  = (const float*)d_in[1];
    const float* iwt = (const float*)d_in[2];
    const float* dww = (const float*)d_in[3];
    const float* dwb = (const float*)d_in[4];
    const float* pw  = (const float*)d_in[5];
    const float* pb  = (const float*)d_in[6];
    const float* ab  = (const float*)d_in[7];
    const int*   bidx= (const int*)d_in[8];
    float* out = (float*)d_out;

    (void)in_sizes; (void)n_in; (void)out_size;

    cudaFuncSetAttribute(k_proj, cudaFuncAttributeMaxDynamicSharedMemorySize, PROJ_SMEM);

    k_wsplit <<<DIM * DIM / 256, 256>>>(pw);
    k_fwt    <<<(NWIN * DIM * 32) / 256, 256>>>(x, wt);
    k_attnmat<<<NWIN * HEADS, 256>>>(dww, dwb, ab, bidx);
    k_vrec   <<<NWIN, 256>>>();
    k_proj   <<<NWIN, 256, PROJ_SMEM>>>();
    k_iwt    <<<(NB * DIM * RES * RES) / 256, 256>>>(iwt, pb, out);
}